// round 4
// baseline (speedup 1.0000x reference)
#include <cuda_runtime.h>
#include <cstdint>

// Problem constants
#define Bn 4
#define Tn 64
#define Fn 32
#define Nn 512
#define Hn 64
#define SROWS 288            // 3*F (X taps) + 3*H (Sz taps)
#define COLS_PER_CTA 16
#define CTAS_PER_B 32
#define NCTAS (Bn * CTAS_PER_B)   // 128 CTAs, 1/SM, all resident
#define NTHREADS 512
#define MB 32                // k-chunk
#define NCHUNK (Nn / MB)     // 16
#define RPT 9                // rows per thread (9 rows x 1 col)

#define PITCH_ST 36          // state tile pitch (floats)
#define PITCH_V  388         // sV pitch (floats)
#define NV       384         // phase-2 vector length

// smem layout (float offsets) — identical to R3
#define OFF_W      0                         // 64 x 384 = 24576
#define OFF_BIAS   24576                     // 64
#define OFF_STATE  24640                     // 2 x (288*36) = 20736
#define ST_BUF     (SROWS * PITCH_ST)        // 10368
#define OFF_SS     45376                     // 2 x (16*36) = 1152
#define SS_BUF     (16 * PITCH_ST)           // 576
#define OFF_V      46528                     // 16 x 388 = 6208
#define SMEM_FLOATS 52736
#define SMEM_BYTES  (SMEM_FLOATS * 4)        // 210944

// Persistent global state
__device__ __align__(16) float g_state[2][Bn][SROWS][Nn];
__device__ unsigned g_count = 0;
__device__ unsigned g_sense = 0;

__device__ __forceinline__ void grid_barrier(unsigned* lsense) {
    __syncthreads();
    if (threadIdx.x == 0) {
        __threadfence();
        unsigned s = (*lsense) ^ 1u;
        *lsense = s;
        unsigned old = atomicAdd(&g_count, 1u);
        if (old == NCTAS - 1u) {
            atomicExch(&g_count, 0u);
            __threadfence();
            atomicExch(&g_sense, s);
        } else {
            while (atomicAdd(&g_sense, 0u) != s) { __nanosleep(64); }
            __threadfence();
        }
    }
    __syncthreads();
}

__device__ __forceinline__ unsigned long long ffma2(unsigned long long a,
                                                    unsigned long long b,
                                                    unsigned long long c) {
    unsigned long long d;
    asm("fma.rn.f32x2 %0, %1, %2, %3;" : "=l"(d) : "l"(a), "l"(b), "l"(c));
    return d;
}
__device__ __forceinline__ float upsum(unsigned long long p) {
    float lo, hi;
    asm("mov.b64 {%0, %1}, %2;" : "=f"(lo), "=f"(hi) : "l"(p));
    return lo + hi;
}
__device__ __forceinline__ void cp_async16(uint32_t dst, const void* src) {
    asm volatile("cp.async.cg.shared.global [%0], [%1], 16;" :: "r"(dst), "l"(src));
}
__device__ __forceinline__ void cp_commit() { asm volatile("cp.async.commit_group;"); }
__device__ __forceinline__ void cp_wait0()  { asm volatile("cp.async.wait_group 0;"); }

__global__ void __launch_bounds__(NTHREADS, 1)
hs_db_kernel(const float* __restrict__ x,      // (B,T,F,N)
             const float* __restrict__ z0,     // (B,H,N)
             const float* __restrict__ S,      // (B,T,1,N,N)
             const float* __restrict__ aW,     // (H,1,K,F)  K*F = 128
             const float* __restrict__ bW,     // (H,1,K,H)  K*H = 256
             const float* __restrict__ xBias,  // (H,1)
             const float* __restrict__ zBias,  // (H,1)
             float* __restrict__ out)          // (B,T,H,N)
{
    extern __shared__ float sm[];
    float* sW    = sm + OFF_W;       // [64][384] = concat(aW row, bW row)
    float* sbias = sm + OFF_BIAS;
    float* sV    = sm + OFF_V;       // [16][388]: [0..31]=x, [32..127]=Y_x, [128..191]=z, [192..383]=Y_sz

    const int tid  = threadIdx.x;
    const int b    = blockIdx.x / CTAS_PER_B;
    const int col0 = (blockIdx.x % CTAS_PER_B) * COLS_PER_CTA;

    // phase-1 compute mapping: thread -> (9 rows, 1 col)
    const int c1  = tid & 15;        // col 0..15
    const int rg  = tid >> 4;        // 0..31
    const int R0  = rg * RPT;        // row base (9 rows)
    // state tile loader mapping (cp.async): 8 segs x rows
    const int seg = tid & 7;         // 16B segment within 128B row chunk
    const int rld = tid >> 3;        // rows rld + 64*it
    // S staging mapping: one element per thread
    const int mmA = tid >> 4;        // 0..31
    const int ccA = tid & 15;
    // phase-2 mapping: thread -> (2 h, 1 col)
    const int hh  = tid >> 4;        // 0..31, h in {hh, hh+32}
    const int cc2 = tid & 15;

    uint32_t smem_base_u32 = (uint32_t)__cvta_generic_to_shared(sm);

    // Load fused weights once: sW[h][0..127]=aW[h], [128..383]=bW[h]
    for (int i = tid; i < Hn * 128; i += NTHREADS) {
        int h = i >> 7, j = i & 127;
        sW[h * NV + j] = aW[i];
    }
    for (int i = tid; i < Hn * 256; i += NTHREADS) {
        int h = i >> 8, j = i & 255;
        sW[h * NV + 128 + j] = bW[i];
    }
    if (tid < Hn) sbias[tid] = xBias[tid] + zBias[tid];

    // Init: state buffer 0 zero (this CTA's columns), sV z-region <- z0
    for (int i = tid; i < SROWS * COLS_PER_CTA; i += NTHREADS) {
        int r = i >> 4, cc = i & 15;
        g_state[0][b][r][col0 + cc] = 0.0f;
    }
    for (int i = tid; i < Hn * COLS_PER_CTA; i += NTHREADS) {
        int g = i >> 4, cc = i & 15;
        sV[cc * PITCH_V + 128 + g] = z0[(b * Hn + g) * Nn + col0 + cc];
    }

    unsigned lsense = 0;
    grid_barrier(&lsense);   // barrier #1

    for (int t = 0; t < Tn; ++t) {
        const int cur = t & 1;
        const int nxt = cur ^ 1;
        const float* Sbt = S + (size_t)(b * Tn + t) * Nn * Nn;
        const float* xbt = x + (size_t)(b * Tn + t) * Fn * Nn;
        const float* gst = &g_state[cur][b][0][0];

        // Stage x(t) -> sV[cc][0..31]  (1 element per thread)
        sV[ccA * PITCH_V + mmA] = xbt[mmA * Nn + col0 + ccA];

        // ---- Phase 1 pipeline prologue: chunk 0 ----
        float sA = Sbt[(size_t)mmA * Nn + col0 + ccA];
#pragma unroll
        for (int it = 0; it < 5; ++it) {
            int r = rld + 64 * it;
            if (r < SROWS) {
                uint32_t dst = smem_base_u32 + (OFF_STATE + r * PITCH_ST + seg * 4) * 4;
                cp_async16(dst, gst + (size_t)r * Nn + seg * 4);
            }
        }
        cp_commit();
        {
            float* ss0 = sm + OFF_SS;
            ss0[ccA * PITCH_ST + mmA] = sA;
        }
        cp_wait0();
        __syncthreads();

        unsigned long long acc[RPT];
#pragma unroll
        for (int r = 0; r < RPT; ++r) acc[r] = 0ull;

        for (int k = 0; k < NCHUNK; ++k) {
            const int buf = k & 1, nb = buf ^ 1;
            // prefetch chunk k+1
            if (k < NCHUNK - 1) {
                const int m1 = (k + 1) * MB;
                sA = Sbt[(size_t)(m1 + mmA) * Nn + col0 + ccA];
#pragma unroll
                for (int it = 0; it < 5; ++it) {
                    int r = rld + 64 * it;
                    if (r < SROWS) {
                        uint32_t dst = smem_base_u32 +
                            (OFF_STATE + nb * ST_BUF + r * PITCH_ST + seg * 4) * 4;
                        cp_async16(dst, gst + (size_t)r * Nn + m1 + seg * 4);
                    }
                }
                cp_commit();
            }
            // compute chunk k
            {
                const float* stb  = sm + OFF_STATE + buf * ST_BUF;
                const float* srow = stb + R0 * PITCH_ST;
                const float* bp   = sm + OFF_SS + buf * SS_BUF + c1 * PITCH_ST;
#pragma unroll
                for (int mm = 0; mm < MB; mm += 4) {
                    ulonglong2 bb = *reinterpret_cast<const ulonglong2*>(bp + mm);
#pragma unroll
                    for (int r = 0; r < RPT; ++r) {
                        ulonglong2 s = *reinterpret_cast<const ulonglong2*>(
                            srow + r * PITCH_ST + mm);
                        acc[r] = ffma2(s.x, bb.x, acc[r]);
                        acc[r] = ffma2(s.y, bb.y, acc[r]);
                    }
                }
            }
            if (k < NCHUNK - 1) {
                cp_wait0();
                float* ssn = sm + OFF_SS + nb * SS_BUF;
                ssn[ccA * PITCH_ST + mmA] = sA;
                __syncthreads();
            }
        }

        // Store Y into transposed sV: row<96 -> j=32+row ; row>=96 -> j=96+row
#pragma unroll
        for (int r = 0; r < RPT; ++r) {
            int row = R0 + r;
            int j = (row < 96) ? (32 + row) : (96 + row);
            sV[c1 * PITCH_V + j] = upsum(acc[r]);
        }
        __syncthreads();

        // ---- Phase 2: pre[h,c] = bias[h] + sum_j sW[h][j] * sV[c][j] ----
        unsigned long long pa[2] = {0ull, 0ull};
        {
            const float* vp = sV + cc2 * PITCH_V;
#pragma unroll 4
            for (int j = 0; j < NV; j += 4) {
                ulonglong2 v = *reinterpret_cast<const ulonglong2*>(vp + j);
#pragma unroll
                for (int i = 0; i < 2; ++i) {
                    ulonglong2 w = *reinterpret_cast<const ulonglong2*>(
                        sW + (hh + 32 * i) * NV + j);
                    pa[i] = ffma2(w.x, v.x, pa[i]);
                    pa[i] = ffma2(w.y, v.y, pa[i]);
                }
            }
        }
        float zv[2];
#pragma unroll
        for (int i = 0; i < 2; ++i)
            zv[i] = tanhf(sbias[hh + 32 * i] + upsum(pa[i]));

        // ---- State shift for t+1 (reads sV, incl. z(t-1) region) ----
        //  rows 0..31   <- x(t)       (sV j=r)
        //  rows 32..95  <- Y[0..63]   (sV j=r)
        //  rows 96..159 <- z(t-1)     (sV j=r+32)
        //  rows 160..287<- Y[96..223] (sV j=r+32)
#pragma unroll
        for (int it = 0; it < 9; ++it) {
            int i = tid + it * NTHREADS;
            int r = i >> 4, cc = i & 15;
            int j = (r < 96) ? r : (r + 32);
            g_state[nxt][b][r][col0 + cc] = sV[cc * PITCH_V + j];
        }
        __syncthreads();   // all reads of z(t-1) done before overwrite

        // write z(t) -> out + sV z-region
#pragma unroll
        for (int i = 0; i < 2; ++i) {
            int h = hh + 32 * i;
            out[(((size_t)b * Tn + t) * Hn + h) * Nn + col0 + cc2] = zv[i];
            sV[cc2 * PITCH_V + 128 + h] = zv[i];
        }

        grid_barrier(&lsense);   // barriers #2..#65
    }

    grid_barrier(&lsense);       // barrier #66 (even parity per launch)
}

extern "C" void kernel_launch(void* const* d_in, const int* in_sizes, int n_in,
                              void* d_out, int out_size) {
    const float* x     = (const float*)d_in[0];
    const float* z0    = (const float*)d_in[1];
    const float* S     = (const float*)d_in[2];
    const float* aW    = (const float*)d_in[3];
    const float* bW    = (const float*)d_in[4];
    const float* xBias = (const float*)d_in[5];
    const float* zBias = (const float*)d_in[6];
    float* out = (float*)d_out;

    cudaFuncSetAttribute(hs_db_kernel,
                         cudaFuncAttributeMaxDynamicSharedMemorySize, SMEM_BYTES);
    hs_db_kernel<<<NCTAS, NTHREADS, SMEM_BYTES>>>(x, z0, S, aW, bW, xBias, zBias, out);
}

// round 5
// speedup vs baseline: 1.0339x; 1.0339x over previous
#include <cuda_runtime.h>
#include <cstdint>

// Problem constants
#define Bn 4
#define Tn 64
#define Fn 32
#define Nn 512
#define Hn 64
#define SROWS 288            // 3*F (X taps) + 3*H (Sz taps)
#define COLS_PER_CTA 16
#define CTAS_PER_B 32
#define NCTAS (Bn * CTAS_PER_B)   // 128 CTAs, 1/SM, all resident
#define NTHREADS 512
#define MB 32                // k-chunk width
#define NCHUNK (Nn / MB)     // 16
#define RPT 9                // rows per thread (9 rows x 1 col)

#define PITCH_SS 36          // S tile pitch (floats)
#define PITCH_V  388         // sV pitch (floats)
#define NV       384         // phase-2 vector length

#define CHUNK_FLOATS (SROWS * MB)          // 9216
#define CHUNK_BYTES  (CHUNK_FLOATS * 4)    // 36864

// smem layout (float offsets)
#define OFF_W      0                         // 64 x 384 = 24576
#define OFF_BIAS   24576                     // 64
#define OFF_MBAR   24640                     // 4 floats (2 x 8B mbarriers)
#define OFF_STATE  24644                     // 2 x 9216 = 18432 (16B aligned)
#define OFF_SS     43076                     // 2 x (16*36) = 1152
#define SS_BUF     (16 * PITCH_SS)           // 576
#define OFF_V      44228                     // 16 x 388 = 6208
#define SMEM_FLOATS 50436
#define SMEM_BYTES  (SMEM_FLOATS * 4)        // 201744

// Persistent global state: chunk-major so each (chunk) tile is contiguous 36KB
__device__ __align__(16) float g_state[2][Bn][NCHUNK][SROWS][MB];
__device__ unsigned g_count = 0;
__device__ unsigned g_sense = 0;

__device__ __forceinline__ void grid_barrier(unsigned* lsense) {
    __syncthreads();
    if (threadIdx.x == 0) {
        __threadfence();
        unsigned s = (*lsense) ^ 1u;
        *lsense = s;
        unsigned old = atomicAdd(&g_count, 1u);
        if (old == NCTAS - 1u) {
            atomicExch(&g_count, 0u);
            __threadfence();
            atomicExch(&g_sense, s);
        } else {
            while (atomicAdd(&g_sense, 0u) != s) { __nanosleep(64); }
            __threadfence();
        }
    }
    __syncthreads();
}

__device__ __forceinline__ unsigned long long ffma2(unsigned long long a,
                                                    unsigned long long b,
                                                    unsigned long long c) {
    unsigned long long d;
    asm("fma.rn.f32x2 %0, %1, %2, %3;" : "=l"(d) : "l"(a), "l"(b), "l"(c));
    return d;
}
__device__ __forceinline__ float upsum(unsigned long long p) {
    float lo, hi;
    asm("mov.b64 {%0, %1}, %2;" : "=f"(lo), "=f"(hi) : "l"(p));
    return lo + hi;
}

// mbarrier helpers
__device__ __forceinline__ void mbar_init(uint32_t addr, uint32_t count) {
    asm volatile("mbarrier.init.shared.b64 [%0], %1;" :: "r"(addr), "r"(count) : "memory");
}
__device__ __forceinline__ void mbar_expect_tx(uint32_t addr, uint32_t bytes) {
    asm volatile("mbarrier.arrive.expect_tx.shared.b64 _, [%0], %1;"
                 :: "r"(addr), "r"(bytes) : "memory");
}
__device__ __forceinline__ void mbar_wait(uint32_t addr, uint32_t parity) {
    uint32_t done;
    asm volatile(
        "{\n\t.reg .pred p;\n\t"
        "mbarrier.try_wait.parity.acquire.cta.shared::cta.b64 p, [%1], %2;\n\t"
        "selp.b32 %0, 1, 0, p;\n\t}"
        : "=r"(done) : "r"(addr), "r"(parity) : "memory");
    if (!done) {
        asm volatile(
            "{\n\t.reg .pred P1;\n\t"
            "WL_%=:\n\t"
            "mbarrier.try_wait.parity.acquire.cta.shared::cta.b64 P1, [%0], %1, 0x989680;\n\t"
            "@P1 bra.uni WD_%=;\n\t"
            "bra.uni WL_%=;\n\t"
            "WD_%=:\n\t}"
            :: "r"(addr), "r"(parity) : "memory");
    }
}
__device__ __forceinline__ void bulk_copy(uint32_t dst_smem, const void* src, uint32_t bytes,
                                          uint32_t mbar) {
    asm volatile(
        "cp.async.bulk.shared::cta.global.mbarrier::complete_tx::bytes [%0], [%1], %2, [%3];"
        :: "r"(dst_smem), "l"(src), "r"(bytes), "r"(mbar) : "memory");
}

__global__ void __launch_bounds__(NTHREADS, 1)
hs_db_kernel(const float* __restrict__ x,      // (B,T,F,N)
             const float* __restrict__ z0,     // (B,H,N)
             const float* __restrict__ S,      // (B,T,1,N,N)
             const float* __restrict__ aW,     // (H,1,K,F)  K*F = 128
             const float* __restrict__ bW,     // (H,1,K,H)  K*H = 256
             const float* __restrict__ xBias,  // (H,1)
             const float* __restrict__ zBias,  // (H,1)
             float* __restrict__ out)          // (B,T,H,N)
{
    extern __shared__ float sm[];
    float* sW    = sm + OFF_W;       // [64][384] = concat(aW row, bW row)
    float* sbias = sm + OFF_BIAS;
    float* sV    = sm + OFF_V;       // [16][388]

    const int tid  = threadIdx.x;
    const int b    = blockIdx.x / CTAS_PER_B;
    const int col0 = (blockIdx.x % CTAS_PER_B) * COLS_PER_CTA;
    const int kc0  = col0 >> 5;          // k-chunk holding this CTA's columns
    const int cmb  = col0 & 31;          // 0 or 16 within that chunk

    // phase-1 compute mapping: thread -> (9 rows, 1 col)
    const int c1  = tid & 15;
    const int rg  = tid >> 4;            // 0..31
    const int R0  = rg * RPT;
    // S staging: one element per thread
    const int mmA = tid >> 4;            // 0..31
    const int ccA = tid & 15;
    // phase-2 mapping: thread -> (2 h, 1 col)
    const int hh  = tid >> 4;
    const int cc2 = tid & 15;

    const uint32_t smem_u32 = (uint32_t)__cvta_generic_to_shared(sm);
    const uint32_t mbar0 = smem_u32 + OFF_MBAR * 4;
    const uint32_t mbar1 = mbar0 + 8;
    const uint32_t st_smem0 = smem_u32 + OFF_STATE * 4;
    const uint32_t st_smem1 = st_smem0 + CHUNK_BYTES;

    if (tid == 0) { mbar_init(mbar0, 1); mbar_init(mbar1, 1); }

    // Load fused weights once
    for (int i = tid; i < Hn * 128; i += NTHREADS) {
        int h = i >> 7, j = i & 127;
        sW[h * NV + j] = aW[i];
    }
    for (int i = tid; i < Hn * 256; i += NTHREADS) {
        int h = i >> 8, j = i & 255;
        sW[h * NV + 128 + j] = bW[i];
    }
    if (tid < Hn) sbias[tid] = xBias[tid] + zBias[tid];

    // Init: state buffer 0 zero (this CTA's columns), sV z-region <- z0
    for (int i = tid; i < SROWS * COLS_PER_CTA; i += NTHREADS) {
        int r = i >> 4, cc = i & 15;
        g_state[0][b][kc0][r][cmb + cc] = 0.0f;
    }
    for (int i = tid; i < Hn * COLS_PER_CTA; i += NTHREADS) {
        int g = i >> 4, cc = i & 15;
        sV[cc * PITCH_V + 128 + g] = z0[(b * Hn + g) * Nn + col0 + cc];
    }

    unsigned lsense = 0;
    unsigned ph0 = 0, ph1 = 0;
    grid_barrier(&lsense);   // barrier #1 (also orders mbarrier init)

    for (int t = 0; t < Tn; ++t) {
        const int cur = t & 1;
        const int nxt = cur ^ 1;
        const float* Sbt = S + (size_t)(b * Tn + t) * Nn * Nn;
        const float* xbt = x + (size_t)(b * Tn + t) * Fn * Nn;
        const float* gst = &g_state[cur][b][0][0][0];

        // Stage x(t) -> sV[cc][0..31]
        sV[ccA * PITCH_V + mmA] = xbt[mmA * Nn + col0 + ccA];

        // ---- prologue: chunk 0 ----
        if (tid == 0) {
            mbar_expect_tx(mbar0, CHUNK_BYTES);
            bulk_copy(st_smem0, gst, CHUNK_BYTES, mbar0);
        }
        float sA = Sbt[(size_t)mmA * Nn + col0 + ccA];
        __syncthreads();
        (sm + OFF_SS)[ccA * PITCH_SS + mmA] = sA;
        __syncthreads();
        mbar_wait(mbar0, ph0); ph0 ^= 1u;

        unsigned long long acc[RPT];
#pragma unroll
        for (int r = 0; r < RPT; ++r) acc[r] = 0ull;

        for (int k = 0; k < NCHUNK; ++k) {
            const int buf = k & 1, nb = buf ^ 1;
            // prefetch chunk k+1
            if (k < NCHUNK - 1) {
                const int m1 = (k + 1) * MB;
                sA = Sbt[(size_t)(m1 + mmA) * Nn + col0 + ccA];
                if (tid == 0) {
                    uint32_t mb = nb ? mbar1 : mbar0;
                    uint32_t ds = nb ? st_smem1 : st_smem0;
                    mbar_expect_tx(mb, CHUNK_BYTES);
                    bulk_copy(ds, gst + (size_t)(k + 1) * CHUNK_FLOATS, CHUNK_BYTES, mb);
                }
            }
            // compute chunk k
            {
                const float* stb  = sm + OFF_STATE + buf * CHUNK_FLOATS;
                const float* srow = stb + R0 * MB;
                const float* bp   = sm + OFF_SS + buf * SS_BUF + c1 * PITCH_SS;
#pragma unroll
                for (int mm = 0; mm < MB; mm += 4) {
                    ulonglong2 bb = *reinterpret_cast<const ulonglong2*>(bp + mm);
#pragma unroll
                    for (int r = 0; r < RPT; ++r) {
                        ulonglong2 s = *reinterpret_cast<const ulonglong2*>(
                            srow + r * MB + mm);
                        acc[r] = ffma2(s.x, bb.x, acc[r]);
                        acc[r] = ffma2(s.y, bb.y, acc[r]);
                    }
                }
            }
            if (k < NCHUNK - 1) {
                __syncthreads();     // all threads done reading ss[nb] (chunk k-1)
                (sm + OFF_SS + nb * SS_BUF)[ccA * PITCH_SS + mmA] = sA;
                __syncthreads();     // ss[nb] visible to all
                if (nb) { mbar_wait(mbar1, ph1); ph1 ^= 1u; }
                else    { mbar_wait(mbar0, ph0); ph0 ^= 1u; }
            }
        }

        // Store Y into transposed sV: row<96 -> j=32+row ; row>=96 -> j=96+row
#pragma unroll
        for (int r = 0; r < RPT; ++r) {
            int row = R0 + r;
            int j = (row < 96) ? (32 + row) : (96 + row);
            sV[c1 * PITCH_V + j] = upsum(acc[r]);
        }
        __syncthreads();

        // ---- Phase 2: pre[h,c] = bias[h] + sum_j sW[h][j] * sV[c][j] ----
        unsigned long long pa[2] = {0ull, 0ull};
        {
            const float* vp = sV + cc2 * PITCH_V;
#pragma unroll 4
            for (int j = 0; j < NV; j += 4) {
                ulonglong2 v = *reinterpret_cast<const ulonglong2*>(vp + j);
#pragma unroll
                for (int i = 0; i < 2; ++i) {
                    ulonglong2 w = *reinterpret_cast<const ulonglong2*>(
                        sW + (hh + 32 * i) * NV + j);
                    pa[i] = ffma2(w.x, v.x, pa[i]);
                    pa[i] = ffma2(w.y, v.y, pa[i]);
                }
            }
        }
        float zv[2];
#pragma unroll
        for (int i = 0; i < 2; ++i)
            zv[i] = tanhf(sbias[hh + 32 * i] + upsum(pa[i]));

        // ---- State shift for t+1 (column-local, new chunk-major layout) ----
        //  rows 0..31   <- x(t)       (sV j=r)
        //  rows 32..95  <- Y[0..63]   (sV j=r)
        //  rows 96..159 <- z(t-1)     (sV j=r+32)
        //  rows 160..287<- Y[96..223] (sV j=r+32)
#pragma unroll
        for (int it = 0; it < 9; ++it) {
            int i = tid + it * NTHREADS;
            int r = i >> 4, cc = i & 15;
            int j = (r < 96) ? r : (r + 32);
            g_state[nxt][b][kc0][r][cmb + cc] = sV[cc * PITCH_V + j];
        }
        __syncthreads();   // all reads of z(t-1) done before overwrite

        // write z(t) -> out + sV z-region
#pragma unroll
        for (int i = 0; i < 2; ++i) {
            int h = hh + 32 * i;
            out[(((size_t)b * Tn + t) * Hn + h) * Nn + col0 + cc2] = zv[i];
            sV[cc2 * PITCH_V + 128 + h] = zv[i];
        }

        grid_barrier(&lsense);   // barriers #2..#65
    }

    grid_barrier(&lsense);       // barrier #66 (even parity per launch)
}

extern "C" void kernel_launch(void* const* d_in, const int* in_sizes, int n_in,
                              void* d_out, int out_size) {
    const float* x     = (const float*)d_in[0];
    const float* z0    = (const float*)d_in[1];
    const float* S     = (const float*)d_in[2];
    const float* aW    = (const float*)d_in[3];
    const float* bW    = (const float*)d_in[4];
    const float* xBias = (const float*)d_in[5];
    const float* zBias = (const float*)d_in[6];
    float* out = (float*)d_out;

    cudaFuncSetAttribute(hs_db_kernel,
                         cudaFuncAttributeMaxDynamicSharedMemorySize, SMEM_BYTES);
    hs_db_kernel<<<NCTAS, NTHREADS, SMEM_BYTES>>>(x, z0, S, aW, bW, xBias, zBias, out);
}

// round 6
// speedup vs baseline: 1.0452x; 1.0109x over previous
#include <cuda_runtime.h>
#include <cstdint>

// Problem constants
#define Bn 4
#define Tn 64
#define Fn 32
#define Nn 512
#define Hn 64
#define SROWS 288
#define COLS_PER_CTA 16
#define CTAS_PER_B 32
#define NCTAS (Bn * CTAS_PER_B)   // 128 CTAs, 1/SM
#define NTHREADS 512
#define MB 32                     // k-chunk width
#define NCHUNK (Nn / MB)          // 16
#define RPT 9

#define PITCH_SS 36
#define PITCH_V  388
#define NV       384
#define PITCH_YP 18

#define CHUNK_FLOATS (SROWS * MB)          // 9216
#define CHUNK_BYTES  (CHUNK_FLOATS * 4)    // 36864

// smem layout (float offsets)
#define OFF_W      0                        // 64*384 = 24576
#define OFF_BIAS   24576                    // 64
#define OFF_MBAR   24640                    // 4
#define OFF_STATE  24644                    // 2*9216 = 18432
#define OFF_SS     43076                    // 2*576 = 1152
#define SS_BUF     (16 * PITCH_SS)          // 576
#define OFF_YP     44228                    // 288*18 = 5184
#define OFF_V      49412                    // 16*388 = 6208
#define SMEM_FLOATS 55620
#define SMEM_BYTES  (SMEM_FLOATS * 4)       // 222480

// Persistent global state, chunk-major, XOR-swizzled within each 32-float row:
// element (row, c) of a chunk lives at row*32 + (((c>>2)^(row&7))<<2 | (c&3))
__device__ __align__(16) float g_state[2][Bn][NCHUNK][SROWS][MB];
__device__ unsigned g_count = 0;
__device__ unsigned g_sense = 0;

__device__ __forceinline__ int swz(int r, int c32) {
    return r * 32 + (((((unsigned)c32 >> 2) ^ ((unsigned)r & 7u)) << 2) | (c32 & 3));
}

__device__ __forceinline__ void grid_barrier(unsigned* lsense) {
    __syncthreads();
    if (threadIdx.x == 0) {
        __threadfence();
        unsigned s = (*lsense) ^ 1u;
        *lsense = s;
        unsigned old = atomicAdd(&g_count, 1u);
        if (old == NCTAS - 1u) {
            atomicExch(&g_count, 0u);
            __threadfence();
            atomicExch(&g_sense, s);
        } else {
            while (atomicAdd(&g_sense, 0u) != s) { __nanosleep(64); }
            __threadfence();
        }
    }
    __syncthreads();
}

__device__ __forceinline__ unsigned long long ffma2(unsigned long long a,
                                                    unsigned long long b,
                                                    unsigned long long c) {
    unsigned long long d;
    asm("fma.rn.f32x2 %0, %1, %2, %3;" : "=l"(d) : "l"(a), "l"(b), "l"(c));
    return d;
}
__device__ __forceinline__ float upsum(unsigned long long p) {
    float lo, hi;
    asm("mov.b64 {%0, %1}, %2;" : "=f"(lo), "=f"(hi) : "l"(p));
    return lo + hi;
}

// mbarrier helpers
__device__ __forceinline__ void mbar_init(uint32_t addr, uint32_t count) {
    asm volatile("mbarrier.init.shared.b64 [%0], %1;" :: "r"(addr), "r"(count) : "memory");
}
__device__ __forceinline__ void mbar_expect_tx(uint32_t addr, uint32_t bytes) {
    asm volatile("mbarrier.arrive.expect_tx.shared.b64 _, [%0], %1;"
                 :: "r"(addr), "r"(bytes) : "memory");
}
__device__ __forceinline__ void mbar_wait(uint32_t addr, uint32_t parity) {
    uint32_t done;
    asm volatile(
        "{\n\t.reg .pred p;\n\t"
        "mbarrier.try_wait.parity.acquire.cta.shared::cta.b64 p, [%1], %2;\n\t"
        "selp.b32 %0, 1, 0, p;\n\t}"
        : "=r"(done) : "r"(addr), "r"(parity) : "memory");
    if (!done) {
        asm volatile(
            "{\n\t.reg .pred P1;\n\t"
            "WL_%=:\n\t"
            "mbarrier.try_wait.parity.acquire.cta.shared::cta.b64 P1, [%0], %1, 0x989680;\n\t"
            "@P1 bra.uni WD_%=;\n\t"
            "bra.uni WL_%=;\n\t"
            "WD_%=:\n\t}"
            :: "r"(addr), "r"(parity) : "memory");
    }
}
__device__ __forceinline__ void bulk_copy(uint32_t dst_smem, const void* src, uint32_t bytes,
                                          uint32_t mbar) {
    asm volatile(
        "cp.async.bulk.shared::cta.global.mbarrier::complete_tx::bytes [%0], [%1], %2, [%3];"
        :: "r"(dst_smem), "l"(src), "r"(bytes), "r"(mbar) : "memory");
}

__global__ void __launch_bounds__(NTHREADS, 1)
hs_db_kernel(const float* __restrict__ x,      // (B,T,F,N)
             const float* __restrict__ z0,     // (B,H,N)
             const float* __restrict__ S,      // (B,T,1,N,N)
             const float* __restrict__ aW,     // (H,1,K,F)
             const float* __restrict__ bW,     // (H,1,K,H)
             const float* __restrict__ xBias,  // (H,1)
             const float* __restrict__ zBias,  // (H,1)
             float* __restrict__ out)          // (B,T,H,N)
{
    extern __shared__ float sm[];
    float* sW    = sm + OFF_W;
    float* sbias = sm + OFF_BIAS;
    float* sV    = sm + OFF_V;
    float* sYp   = sm + OFF_YP;

    const int tid  = threadIdx.x;
    const int b    = blockIdx.x / CTAS_PER_B;
    const int col0 = (blockIdx.x % CTAS_PER_B) * COLS_PER_CTA;
    const int kc0  = col0 >> 5;
    const int cmb  = col0 & 31;

    // phase-1 mapping: 2 k-groups of 256 threads; tile = 9 rows x 2 cols
    const int kg   = tid >> 8;            // 0/1: handles mm in [16*kg, 16*kg+16)
    const int t256 = tid & 255;
    const int cgp  = t256 & 7;            // col pair -> cols 2cgp, 2cgp+1
    const int c0   = 2 * cgp;
    const int RG   = t256 >> 3;           // 0..31
    const int R0   = RG * RPT;
    // S staging: one element per thread (32 mm x 16 cols)
    const int mmA = tid >> 4;             // 0..31
    const int ccA = tid & 15;
    // phase-2 mapping
    const int hh  = tid >> 4;
    const int cc2 = tid & 15;

    const uint32_t smem_u32 = (uint32_t)__cvta_generic_to_shared(sm);
    const uint32_t mbar0 = smem_u32 + OFF_MBAR * 4;
    const uint32_t mbar1 = mbar0 + 8;
    const uint32_t st_smem0 = smem_u32 + OFF_STATE * 4;
    const uint32_t st_smem1 = st_smem0 + CHUNK_BYTES;

    if (tid == 0) { mbar_init(mbar0, 1); mbar_init(mbar1, 1); }

    // per-thread constant row swizzle keys and row offsets
    int xr[RPT], roff[RPT];
#pragma unroll
    for (int r = 0; r < RPT; ++r) {
        xr[r]   = (RG + r) & 7;            // (9*RG + r) & 7
        roff[r] = (R0 + r) * 32;
    }

    // Load fused weights
    for (int i = tid; i < Hn * 128; i += NTHREADS) {
        int h = i >> 7, j = i & 127;
        sW[h * NV + j] = aW[i];
    }
    for (int i = tid; i < Hn * 256; i += NTHREADS) {
        int h = i >> 8, j = i & 255;
        sW[h * NV + 128 + j] = bW[i];
    }
    if (tid < Hn) sbias[tid] = xBias[tid] + zBias[tid];

    // Init: zero this CTA's swizzled state columns; sV z-region <- z0
    for (int i = tid; i < SROWS * COLS_PER_CTA; i += NTHREADS) {
        int r = i >> 4, cc = i & 15;
        g_state[0][b][kc0][0][swz(r, cmb + cc)] = 0.0f;
    }
    for (int i = tid; i < Hn * COLS_PER_CTA; i += NTHREADS) {
        int g = i >> 4, cc = i & 15;
        sV[cc * PITCH_V + 128 + g] = z0[(b * Hn + g) * Nn + col0 + cc];
    }

    unsigned lsense = 0;
    unsigned ph0 = 0, ph1 = 0;
    grid_barrier(&lsense);   // barrier #1

    for (int t = 0; t < Tn; ++t) {
        const int cur = t & 1;
        const int nxt = cur ^ 1;
        const float* Sbt = S + (size_t)(b * Tn + t) * Nn * Nn;
        const float* xbt = x + (size_t)(b * Tn + t) * Fn * Nn;
        const float* gst = &g_state[cur][b][0][0][0];

        // Stage x(t) -> sV[cc][0..31]
        sV[ccA * PITCH_V + mmA] = xbt[mmA * Nn + col0 + ccA];

        // prologue: chunk 0
        if (tid == 0) {
            mbar_expect_tx(mbar0, CHUNK_BYTES);
            bulk_copy(st_smem0, gst, CHUNK_BYTES, mbar0);
        }
        float sA = Sbt[(size_t)mmA * Nn + col0 + ccA];
        __syncthreads();
        (sm + OFF_SS)[ccA * PITCH_SS + mmA] = sA;
        __syncthreads();
        mbar_wait(mbar0, ph0); ph0 ^= 1u;

        unsigned long long acc[RPT][2];
#pragma unroll
        for (int r = 0; r < RPT; ++r) { acc[r][0] = 0ull; acc[r][1] = 0ull; }

        for (int k = 0; k < NCHUNK; ++k) {
            const int buf = k & 1, nb = buf ^ 1;
            if (k < NCHUNK - 1) {
                const int m1 = (k + 1) * MB;
                sA = Sbt[(size_t)(m1 + mmA) * Nn + col0 + ccA];
                if (tid == 0) {
                    uint32_t mb = nb ? mbar1 : mbar0;
                    uint32_t ds = nb ? st_smem1 : st_smem0;
                    mbar_expect_tx(mb, CHUNK_BYTES);
                    bulk_copy(ds, gst + (size_t)(k + 1) * CHUNK_FLOATS, CHUNK_BYTES, mb);
                }
            }
            // compute this group's quarter of the chunk's k-range
            {
                const float* stb = sm + OFF_STATE + buf * CHUNK_FLOATS;
                const float* ssb = sm + OFF_SS + buf * SS_BUF;
#pragma unroll
                for (int s = 0; s < 4; ++s) {
                    const int mm  = 16 * kg + 4 * s;
                    const int seg = 4 * kg + s;
                    ulonglong2 b0 = *reinterpret_cast<const ulonglong2*>(
                        ssb + c0 * PITCH_SS + mm);
                    ulonglong2 b1 = *reinterpret_cast<const ulonglong2*>(
                        ssb + (c0 + 1) * PITCH_SS + mm);
#pragma unroll
                    for (int r = 0; r < RPT; ++r) {
                        const ulonglong2 sv = *reinterpret_cast<const ulonglong2*>(
                            stb + roff[r] + ((seg ^ xr[r]) << 2));
                        acc[r][0] = ffma2(sv.x, b0.x, acc[r][0]);
                        acc[r][1] = ffma2(sv.x, b1.x, acc[r][1]);
                        acc[r][0] = ffma2(sv.y, b0.y, acc[r][0]);
                        acc[r][1] = ffma2(sv.y, b1.y, acc[r][1]);
                    }
                }
            }
            if (k < NCHUNK - 1) {
                __syncthreads();
                (sm + OFF_SS + nb * SS_BUF)[ccA * PITCH_SS + mmA] = sA;
                __syncthreads();
                if (nb) { mbar_wait(mbar1, ph1); ph1 ^= 1u; }
                else    { mbar_wait(mbar0, ph0); ph0 ^= 1u; }
            }
        }

        // Reduce the two k-group partials; write Y into transposed sV
        __syncthreads();
        if (kg == 1) {
#pragma unroll
            for (int r = 0; r < RPT; ++r) {
                sYp[(R0 + r) * PITCH_YP + c0]     = upsum(acc[r][0]);
                sYp[(R0 + r) * PITCH_YP + c0 + 1] = upsum(acc[r][1]);
            }
        }
        __syncthreads();
        if (kg == 0) {
#pragma unroll
            for (int r = 0; r < RPT; ++r) {
                int row = R0 + r;
                int j = (row < 96) ? (32 + row) : (96 + row);
                sV[c0 * PITCH_V + j] =
                    upsum(acc[r][0]) + sYp[row * PITCH_YP + c0];
                sV[(c0 + 1) * PITCH_V + j] =
                    upsum(acc[r][1]) + sYp[row * PITCH_YP + c0 + 1];
            }
        }
        __syncthreads();

        // Phase 2: pre[h,c] = bias[h] + sum_j sW[h][j] * sV[c][j]
        unsigned long long pa[2] = {0ull, 0ull};
        {
            const float* vp = sV + cc2 * PITCH_V;
#pragma unroll 4
            for (int j = 0; j < NV; j += 4) {
                ulonglong2 v = *reinterpret_cast<const ulonglong2*>(vp + j);
#pragma unroll
                for (int i = 0; i < 2; ++i) {
                    ulonglong2 w = *reinterpret_cast<const ulonglong2*>(
                        sW + (hh + 32 * i) * NV + j);
                    pa[i] = ffma2(w.x, v.x, pa[i]);
                    pa[i] = ffma2(w.y, v.y, pa[i]);
                }
            }
        }
        float zv[2];
#pragma unroll
        for (int i = 0; i < 2; ++i)
            zv[i] = tanhf(sbias[hh + 32 * i] + upsum(pa[i]));

        // State shift for t+1 (swizzled global writes, column-local)
        float* gnxt = &g_state[nxt][b][kc0][0][0];
#pragma unroll
        for (int it = 0; it < 9; ++it) {
            int i = tid + it * NTHREADS;
            int r = i >> 4, cc = i & 15;
            int j = (r < 96) ? r : (r + 32);
            gnxt[swz(r, cmb + cc)] = sV[cc * PITCH_V + j];
        }
        __syncthreads();   // reads of z(t-1) from sV done before overwrite

        // write z(t) -> out + sV z-region
#pragma unroll
        for (int i = 0; i < 2; ++i) {
            int h = hh + 32 * i;
            out[(((size_t)b * Tn + t) * Hn + h) * Nn + col0 + cc2] = zv[i];
            sV[cc2 * PITCH_V + 128 + h] = zv[i];
        }

        grid_barrier(&lsense);   // barriers #2..#65
    }

    grid_barrier(&lsense);       // barrier #66 (even parity)
}

extern "C" void kernel_launch(void* const* d_in, const int* in_sizes, int n_in,
                              void* d_out, int out_size) {
    const float* x     = (const float*)d_in[0];
    const float* z0    = (const float*)d_in[1];
    const float* S     = (const float*)d_in[2];
    const float* aW    = (const float*)d_in[3];
    const float* bW    = (const float*)d_in[4];
    const float* xBias = (const float*)d_in[5];
    const float* zBias = (const float*)d_in[6];
    float* out = (float*)d_out;

    cudaFuncSetAttribute(hs_db_kernel,
                         cudaFuncAttributeMaxDynamicSharedMemorySize, SMEM_BYTES);
    hs_db_kernel<<<NCTAS, NTHREADS, SMEM_BYTES>>>(x, z0, S, aW, bW, xBias, zBias, out);
}